// round 14
// baseline (speedup 1.0000x reference)
#include <cuda_runtime.h>
#include <cstdint>

#define Tq   1024
#define F_IN 64
#define HDIM 40
#define G4   160

typedef unsigned long long ull;

// ---- global scratch (no allocation allowed; __device__ arrays) ----
__device__ float g_xa[(size_t)512 * Tq * G4];     // seq @ WaK + ba
__device__ float g_xb[(size_t)512 * Tq * G4];     // hs  @ WbK + bb
__device__ float g_hs[(size_t)512 * Tq * HDIM];   // LSTM A outputs

// ---------------------------------------------------------------------------
// Packed f32x2 helpers
// ---------------------------------------------------------------------------
__device__ __forceinline__ ull pack2(float a, float b) {
    ull r; asm("mov.b64 %0, {%1,%2};" : "=l"(r) : "f"(a), "f"(b)); return r;
}
__device__ __forceinline__ void unpack2(ull v, float& a, float& b) {
    asm("mov.b64 {%0,%1}, %2;" : "=f"(a), "=f"(b) : "l"(v));
}
__device__ __forceinline__ void ffma2(ull& d, ull a, ull b) {
    asm("fma.rn.f32x2 %0, %1, %2, %0;" : "+l"(d) : "l"(a), "l"(b));
}

// ---------------------------------------------------------------------------
// MUFU activations
// ---------------------------------------------------------------------------
__device__ __forceinline__ float sigmoid_f(float x) {
    float e, r;
    asm("ex2.approx.f32 %0, %1;" : "=f"(e) : "f"(-1.4426950408889634f * x));
    asm("rcp.approx.f32 %0, %1;" : "=f"(r) : "f"(1.0f + e));
    return r;
}
__device__ __forceinline__ float tanh_f(float x) {
    float e, r;
    asm("ex2.approx.f32 %0, %1;" : "=f"(e) : "f"(2.8853900817779268f * x));
    asm("rcp.approx.f32 %0, %1;" : "=f"(r) : "f"(1.0f + e));
    return 1.0f - 2.0f * r;
}
__device__ __forceinline__ float gate_act(float z, float mm, float aa, float bb) {
    float e, r;
    asm("ex2.approx.f32 %0, %1;" : "=f"(e) : "f"(mm * z));
    asm("rcp.approx.f32 %0, %1;" : "=f"(r) : "f"(1.0f + e));
    return fmaf(aa, r, bb);
}

__device__ __forceinline__ unsigned smem_u32(const void* p) {
    return (unsigned)__cvta_generic_to_shared(p);
}

// ===========================================================================
// K1: xa[b,t,g] = seq[b,t,:]·WaK[:,g] + ba[g].  (verified R13)
// ===========================================================================
__global__ void __launch_bounds__(80)
xa_gemm(const float* __restrict__ seq, const float* __restrict__ WaK,
        const float* __restrict__ ba)
{
    __shared__ __align__(16) float4 sx[32 * 16];   // 32 rows x 64 floats = 8KB
    const int b = blockIdx.x, ch = blockIdx.y, g0 = threadIdx.x, g1 = g0 + 80;

    ull wA[32], wB[32];
    #pragma unroll
    for (int p = 0; p < 32; p++) {
        wA[p] = pack2(WaK[(2 * p) * G4 + g0], WaK[(2 * p + 1) * G4 + g0]);
        wB[p] = pack2(WaK[(2 * p) * G4 + g1], WaK[(2 * p + 1) * G4 + g1]);
    }
    const float bias0 = ba[g0], bias1 = ba[g1];

    const size_t base = (size_t)b * Tq + (size_t)ch * 256;
    const float4* src = (const float4*)(seq + base * F_IN);
    float* op0 = g_xa + base * G4 + g0;
    float* op1 = g_xa + base * G4 + g1;

    for (int tile = 0; tile < 8; tile++) {
        const float4* s4 = src + (size_t)tile * 512;
        for (int idx = g0; idx < 512; idx += 80) sx[idx] = s4[idx];
        __syncthreads();

        for (int r = 0; r < 32; r += 2) {
            const ulonglong2* r0 = (const ulonglong2*)&sx[r * 16];
            const ulonglong2* r1 = (const ulonglong2*)&sx[(r + 1) * 16];
            ull a0 = 0, a1 = 0, b0 = 0, b1 = 0, c0 = 0, c1 = 0, d0 = 0, d1 = 0;
            #pragma unroll
            for (int p = 0; p < 16; p++) {
                ulonglong2 v0 = r0[p], v1 = r1[p];
                ffma2(a0, wA[2 * p],     v0.x);
                ffma2(a1, wA[2 * p + 1], v0.y);
                ffma2(b0, wA[2 * p],     v1.x);
                ffma2(b1, wA[2 * p + 1], v1.y);
                ffma2(c0, wB[2 * p],     v0.x);
                ffma2(c1, wB[2 * p + 1], v0.y);
                ffma2(d0, wB[2 * p],     v1.x);
                ffma2(d1, wB[2 * p + 1], v1.y);
            }
            const int t = tile * 32 + r;
            float x0, x1, x2, x3;
            unpack2(a0, x0, x1); unpack2(a1, x2, x3);
            op0[(size_t)t * G4]       = bias0 + ((x0 + x2) + (x1 + x3));
            unpack2(b0, x0, x1); unpack2(b1, x2, x3);
            op0[(size_t)(t + 1) * G4] = bias0 + ((x0 + x2) + (x1 + x3));
            unpack2(c0, x0, x1); unpack2(c1, x2, x3);
            op1[(size_t)t * G4]       = bias1 + ((x0 + x2) + (x1 + x3));
            unpack2(d0, x0, x1); unpack2(d1, x2, x3);
            op1[(size_t)(t + 1) * G4] = bias1 + ((x0 + x2) + (x1 + x3));
        }
        __syncthreads();
    }
}

// ===========================================================================
// K3: xb[b,t,g] for g in [80,160) ONLY — cols 0-79 are produced inline by
// recur_a. 80 threads, 1 col/thread, 2 rows in flight.
// ===========================================================================
__global__ void __launch_bounds__(80)
xb_gemm_half(const float* __restrict__ WbK, const float* __restrict__ bb)
{
    __shared__ __align__(16) float4 sh4[64 * 10];  // 64 rows x 40 floats = 10KB
    const int b = blockIdx.x, ch = blockIdx.y;
    const int g = 80 + threadIdx.x;

    ull wA[20];
    #pragma unroll
    for (int p = 0; p < 20; p++)
        wA[p] = pack2(WbK[(2 * p) * G4 + g], WbK[(2 * p + 1) * G4 + g]);
    const float bias = bb[g];

    const size_t base = (size_t)b * Tq + (size_t)ch * 256;
    const float4* src = (const float4*)(g_hs + base * HDIM);
    float* op = g_xb + base * G4 + g;

    for (int tile = 0; tile < 4; tile++) {
        const float4* s4 = src + (size_t)tile * 640;
        #pragma unroll
        for (int i = 0; i < 8; i++) sh4[threadIdx.x + i * 80] = s4[threadIdx.x + i * 80];
        __syncthreads();

        for (int r = 0; r < 64; r += 2) {
            const ulonglong2* r0 = (const ulonglong2*)&sh4[r * 10];
            const ulonglong2* r1 = (const ulonglong2*)&sh4[(r + 1) * 10];
            ull a0 = 0, a1 = 0, b0 = 0, b1 = 0;
            #pragma unroll
            for (int p = 0; p < 10; p++) {
                ulonglong2 v0 = r0[p], v1 = r1[p];
                ffma2(a0, wA[2 * p],     v0.x);
                ffma2(a1, wA[2 * p + 1], v0.y);
                ffma2(b0, wA[2 * p],     v1.x);
                ffma2(b1, wA[2 * p + 1], v1.y);
            }
            const int t = tile * 64 + r;
            float x0, x1, x2, x3;
            unpack2(a0, x0, x1); unpack2(a1, x2, x3);
            op[(size_t)t * G4]       = bias + ((x0 + x2) + (x1 + x3));
            unpack2(b0, x0, x1); unpack2(b1, x2, x3);
            op[(size_t)(t + 1) * G4] = bias + ((x0 + x2) + (x1 + x3));
        }
        __syncthreads();
    }
}

// ===========================================================================
// K2: LSTM A recurrence (verified R10 core) + INLINE xb cols 0-79.
// Lane-pair split: lanes l and l^16 of warp w share xb column cb=w*16+(l&15);
// each holds half the column weights (10 f32x2 = 20 regs), half-dots combined
// with one shfl_xor(16). h values come from the same smem the recurrence dot
// reads. At iteration t (>=1) this produces xb[t-1]; the final row is done in
// an epilogue. launch_bounds(160,4) pins the 4-blocks/SM occupancy.
// ===========================================================================
__global__ void __launch_bounds__(160, 4)
recur_a(const float* __restrict__ Wr,
        const float* __restrict__ WbK, const float* __restrict__ bb)
{
    __shared__ __align__(16) float sxa[8][G4];
    __shared__ __align__(16) float sh[2][HDIM];

    const int b = blockIdx.x, tid = threadIdx.x;
    const int lane = tid & 31, q = lane >> 3, u = lane & 7, w = tid >> 5;
    const int j = w * 8 + u;
    const int col = q * HDIM + j;

    const bool isG = (q == 2);
    const float mm  = isG ? -2.8853900817779268f : -1.4426950408889634f;
    const float aa  = isG ? 2.0f : 1.0f;
    const float bbv = isG ? -1.0f : 0.0f;

    ull wr2[20];
    #pragma unroll
    for (int p = 0; p < 20; p++)
        wr2[p] = pack2(Wr[(2 * p) * G4 + col], Wr[(2 * p + 1) * G4 + col]);

    // ---- inline-xb assignment: col cb (0..79), this lane's half of h ----
    const int cb   = w * 16 + (lane & 15);
    const int half = lane >> 4;              // 0: h[0:20), 1: h[20:40)
    ull wb2[10];
    #pragma unroll
    for (int p = 0; p < 10; p++) {
        const int row = half * 20 + 2 * p;
        wb2[p] = pack2(WbK[row * G4 + cb], WbK[(row + 1) * G4 + cb]);
    }
    const float biasb = (half == 0) ? bb[cb] : 0.0f;

    float c = 0.0f;
    if (tid < HDIM) sh[0][tid] = 0.0f;

    const float* srcb = g_xa + (size_t)b * Tq * G4;
    float* xbp = g_xb + (size_t)b * Tq * G4 + cb;

    if (tid < 40) {
        #pragma unroll
        for (int p = 0; p < 4; p++) {
            unsigned dst = smem_u32(&sxa[p][tid * 4]);
            asm volatile("cp.async.ca.shared.global [%0], [%1], 16;\n\t"
                         "cp.async.commit_group;\n"
                         :: "r"(dst), "l"(srcb + (size_t)p * G4 + tid * 4));
        }
        asm volatile("cp.async.wait_group 3;");
    }
    __syncthreads();

    for (int t = 0; t < Tq; t++) {
        if (tid < 40) {
            const int tf = t + 4;
            if (tf < Tq) {
                unsigned dst = smem_u32(&sxa[tf & 7][tid * 4]);
                asm volatile("cp.async.ca.shared.global [%0], [%1], 16;"
                             :: "r"(dst), "l"(srcb + (size_t)tf * G4 + tid * 4));
            }
            asm volatile("cp.async.commit_group;\n\t"
                         "cp.async.wait_group 3;\n");
        }

        const float xz = sxa[t & 7][col];
        const ulonglong2* h2 = (const ulonglong2*)sh[t & 1];
        ull a0 = 0ull, a1 = 0ull;
        #pragma unroll
        for (int p = 0; p < 10; p++) {
            ulonglong2 hv = h2[p];
            ffma2(a0, wr2[2 * p],     hv.x);
            ffma2(a1, wr2[2 * p + 1], hv.y);
        }
        float x0, x1, x2, x3;
        unpack2(a0, x0, x1); unpack2(a1, x2, x3);
        const float z = xz + ((x0 + x2) + (x1 + x3));
        const float v = gate_act(z, mm, aa, bbv);

        // ---- inline xb[t-1][cb]: half-dot over this lane's h half ----
        if (t >= 1) {
            const ulonglong2* hx = h2 + half * 5;
            ull e0 = 0ull, e1 = 0ull;
            #pragma unroll
            for (int p = 0; p < 5; p++) {
                ulonglong2 hv = hx[p];
                ffma2(e0, wb2[2 * p],     hv.x);
                ffma2(e1, wb2[2 * p + 1], hv.y);
            }
            float y0, y1, y2, y3;
            unpack2(e0, y0, y1); unpack2(e1, y2, y3);
            float xv = biasb + ((y0 + y2) + (y1 + y3));
            xv += __shfl_xor_sync(0xffffffffu, xv, 16);
            if (half == 0) xbp[(size_t)(t - 1) * G4] = xv;
        }

        const float fv = __shfl_xor_sync(0xffffffffu, v, 8);
        const float gv = __shfl_xor_sync(0xffffffffu, v, 16);
        const float ov = __shfl_xor_sync(0xffffffffu, v, 24);
        if (q == 0) {
            c = fmaf(fv, c, v * gv);
            const float h = ov * tanh_f(c);
            sh[(t + 1) & 1][j] = h;
            g_hs[((size_t)b * Tq + t) * HDIM + j] = h;
        }
        __syncthreads();
    }

    // ---- epilogue: xb[Tq-1][cb] from the final h ----
    {
        const ulonglong2* h2 = (const ulonglong2*)sh[Tq & 1];
        const ulonglong2* hx = h2 + half * 5;
        ull e0 = 0ull, e1 = 0ull;
        #pragma unroll
        for (int p = 0; p < 5; p++) {
            ulonglong2 hv = hx[p];
            ffma2(e0, wb2[2 * p],     hv.x);
            ffma2(e1, wb2[2 * p + 1], hv.y);
        }
        float y0, y1, y2, y3;
        unpack2(e0, y0, y1); unpack2(e1, y2, y3);
        float xv = biasb + ((y0 + y2) + (y1 + y3));
        xv += __shfl_xor_sync(0xffffffffu, xv, 16);
        if (half == 0) xbp[(size_t)(Tq - 1) * G4] = xv;
    }
}

// ===========================================================================
// K4: LSTM B recurrence + fused dense tail.  (verified R13, 441us)
// ===========================================================================
__global__ void __launch_bounds__(160)
recur_b_tail(const float* __restrict__ Wr,
             const float* __restrict__ feat,
             const float* __restrict__ Wg, const float* __restrict__ bg,
             const float* __restrict__ Wh, const float* __restrict__ bh,
             const float* __restrict__ Wc, const float* __restrict__ bc,
             const float* __restrict__ Wd, const float* __restrict__ bd,
             const float* __restrict__ Wo, const float* __restrict__ bo,
             float* __restrict__ out)
{
    __shared__ __align__(16) float sxa[8][G4];
    __shared__ __align__(16) float sh[2][HDIM];
    __shared__ float t1[10], yy[10], cc[20], dd[10];

    const int b = blockIdx.x, tid = threadIdx.x;
    const int lane = tid & 31, q = lane >> 3, u = lane & 7, w = tid >> 5;
    const int j = w * 8 + u;
    const int col = q * HDIM + j;

    const bool isG = (q == 2);
    const float mm  = isG ? -2.8853900817779268f : -1.4426950408889634f;
    const float aa  = isG ? 2.0f : 1.0f;
    const float bbv = isG ? -1.0f : 0.0f;

    ull wr2[20];
    #pragma unroll
    for (int p = 0; p < 20; p++)
        wr2[p] = pack2(Wr[(2 * p) * G4 + col], Wr[(2 * p + 1) * G4 + col]);

    float c = 0.0f;
    if (tid < HDIM) sh[0][tid] = 0.0f;

    const float* srcb = g_xb + (size_t)b * Tq * G4;

    if (tid < 40) {
        #pragma unroll
        for (int p = 0; p < 4; p++) {
            unsigned dst = smem_u32(&sxa[p][tid * 4]);
            asm volatile("cp.async.ca.shared.global [%0], [%1], 16;\n\t"
                         "cp.async.commit_group;\n"
                         :: "r"(dst), "l"(srcb + (size_t)p * G4 + tid * 4));
        }
        asm volatile("cp.async.wait_group 3;");
    }
    __syncthreads();

    for (int t = 0; t < Tq; t++) {
        if (tid < 40) {
            const int tf = t + 4;
            if (tf < Tq) {
                unsigned dst = smem_u32(&sxa[tf & 7][tid * 4]);
                asm volatile("cp.async.ca.shared.global [%0], [%1], 16;"
                             :: "r"(dst), "l"(srcb + (size_t)tf * G4 + tid * 4));
            }
            asm volatile("cp.async.commit_group;\n\t"
                         "cp.async.wait_group 3;\n");
        }

        const float xz = sxa[t & 7][col];
        const ulonglong2* h2 = (const ulonglong2*)sh[t & 1];
        ull a0 = 0ull, a1 = 0ull;
        #pragma unroll
        for (int p = 0; p < 10; p++) {
            ulonglong2 hv = h2[p];
            ffma2(a0, wr2[2 * p],     hv.x);
            ffma2(a1, wr2[2 * p + 1], hv.y);
        }
        float x0, x1, x2, x3;
        unpack2(a0, x0, x1); unpack2(a1, x2, x3);
        const float z = xz + ((x0 + x2) + (x1 + x3));
        const float v = gate_act(z, mm, aa, bbv);

        const float fv = __shfl_xor_sync(0xffffffffu, v, 8);
        const float gv = __shfl_xor_sync(0xffffffffu, v, 16);
        const float ov = __shfl_xor_sync(0xffffffffu, v, 24);
        if (q == 0) {
            c = fmaf(fv, c, v * gv);
            sh[(t + 1) & 1][j] = ov * tanh_f(c);
        }
        __syncthreads();
    }

    // ---- fused dense tail for row b ----
    const float* hb = sh[Tq & 1];
    const float* fb = feat + (size_t)b * F_IN;
    if (tid < 10) {
        float a = bg[tid];
        #pragma unroll 8
        for (int k = 0; k < F_IN; k++) a = fmaf(fb[k], Wg[k * 10 + tid], a);
        t1[tid] = tanh_f(a);
    }
    __syncthreads();
    if (tid < 10) {
        float a = bh[tid];
        #pragma unroll
        for (int k = 0; k < 10; k++) a = fmaf(t1[k], Wh[k * 10 + tid], a);
        yy[tid] = tanh_f(a);
    }
    __syncthreads();
    if (tid < 20) {
        float a = bc[tid];
        #pragma unroll
        for (int k = 0; k < HDIM; k++) a = fmaf(hb[k], Wc[k * 20 + tid], a);
        #pragma unroll
        for (int k = 0; k < 10; k++)   a = fmaf(yy[k], Wc[(HDIM + k) * 20 + tid], a);
        cc[tid] = fmaxf(a, 0.0f);
    }
    __syncthreads();
    if (tid < 10) {
        float a = bd[tid];
        #pragma unroll
        for (int k = 0; k < 20; k++) a = fmaf(cc[k], Wd[k * 10 + tid], a);
        dd[tid] = fmaxf(a, 0.0f);
    }
    __syncthreads();
    if (tid == 0) {
        float a = bo[0];
        #pragma unroll
        for (int k = 0; k < 10; k++) a = fmaf(dd[k], Wo[k], a);
        out[b] = sigmoid_f(a);
    }
}

// ---------------------------------------------------------------------------
extern "C" void kernel_launch(void* const* d_in, const int* in_sizes, int n_in,
                              void* d_out, int out_size)
{
    (void)in_sizes; (void)n_in; (void)out_size;
    const float* seq  = (const float*)d_in[0];
    const float* feat = (const float*)d_in[1];
    const float* WaK  = (const float*)d_in[2];
    const float* WaR  = (const float*)d_in[3];
    const float* ba   = (const float*)d_in[4];
    const float* WbK  = (const float*)d_in[5];
    const float* WbR  = (const float*)d_in[6];
    const float* bb   = (const float*)d_in[7];
    const float* Wg   = (const float*)d_in[8];
    const float* bg   = (const float*)d_in[9];
    const float* Wh   = (const float*)d_in[10];
    const float* bh   = (const float*)d_in[11];
    const float* Wc   = (const float*)d_in[12];
    const float* bc   = (const float*)d_in[13];
    const float* Wd   = (const float*)d_in[14];
    const float* bd   = (const float*)d_in[15];
    const float* Wo   = (const float*)d_in[16];
    const float* bo   = (const float*)d_in[17];
    float* out = (float*)d_out;

    xa_gemm<<<dim3(512, 4), 80>>>(seq, WaK, ba);
    recur_a<<<512, 160>>>(WaR, WbK, bb);
    xb_gemm_half<<<dim3(512, 4), 80>>>(WbK, bb);
    recur_b_tail<<<512, 160>>>(WbR, feat, Wg, bg, Wh, bh, Wc, bc,
                               Wd, bd, Wo, bo, out);
}

// round 16
// speedup vs baseline: 1.2531x; 1.2531x over previous
#include <cuda_runtime.h>
#include <cuda_fp16.h>
#include <cstdint>

#define Tq   1024
#define F_IN 64
#define HDIM 40
#define G4   160

typedef unsigned long long ull;
typedef unsigned int uint;

// ---- global scratch (no allocation allowed; __device__ arrays) ----
__device__ float g_xa[(size_t)512 * Tq * G4];     // seq @ WaK + ba
__device__ float g_xb[(size_t)512 * Tq * G4];     // hs  @ WbK + bb
__device__ float g_hs[(size_t)512 * Tq * HDIM];   // LSTM A outputs

// ---------------------------------------------------------------------------
// Packed f32x2 helpers (recurrence kernels)
// ---------------------------------------------------------------------------
__device__ __forceinline__ ull pack2(float a, float b) {
    ull r; asm("mov.b64 %0, {%1,%2};" : "=l"(r) : "f"(a), "f"(b)); return r;
}
__device__ __forceinline__ void unpack2(ull v, float& a, float& b) {
    asm("mov.b64 {%0,%1}, %2;" : "=f"(a), "=f"(b) : "l"(v));
}
__device__ __forceinline__ void ffma2(ull& d, ull a, ull b) {
    asm("fma.rn.f32x2 %0, %1, %2, %0;" : "+l"(d) : "l"(a), "l"(b));
}

// ---------------------------------------------------------------------------
// MUFU activations
// ---------------------------------------------------------------------------
__device__ __forceinline__ float sigmoid_f(float x) {
    float e, r;
    asm("ex2.approx.f32 %0, %1;" : "=f"(e) : "f"(-1.4426950408889634f * x));
    asm("rcp.approx.f32 %0, %1;" : "=f"(r) : "f"(1.0f + e));
    return r;
}
__device__ __forceinline__ float tanh_f(float x) {
    float e, r;
    asm("ex2.approx.f32 %0, %1;" : "=f"(e) : "f"(2.8853900817779268f * x));
    asm("rcp.approx.f32 %0, %1;" : "=f"(r) : "f"(1.0f + e));
    return 1.0f - 2.0f * r;
}
__device__ __forceinline__ float gate_act(float z, float mm, float aa, float bb) {
    float e, r;
    asm("ex2.approx.f32 %0, %1;" : "=f"(e) : "f"(mm * z));
    asm("rcp.approx.f32 %0, %1;" : "=f"(r) : "f"(1.0f + e));
    return fmaf(aa, r, bb);
}

__device__ __forceinline__ unsigned smem_u32(const void* p) {
    return (unsigned)__cvta_generic_to_shared(p);
}

// ---------------------------------------------------------------------------
// Tensor-core helpers: m16n8k16 fp16 MMA with fp32 accumulate, split-fp16.
// ---------------------------------------------------------------------------
__device__ __forceinline__ void mma16816(float& c0, float& c1, float& c2, float& c3,
                                         uint a0, uint a1, uint a2, uint a3,
                                         uint b0, uint b1) {
    asm volatile(
        "mma.sync.aligned.m16n8k16.row.col.f32.f16.f16.f32 "
        "{%0,%1,%2,%3}, {%4,%5,%6,%7}, {%8,%9}, {%0,%1,%2,%3};"
        : "+f"(c0), "+f"(c1), "+f"(c2), "+f"(c3)
        : "r"(a0), "r"(a1), "r"(a2), "r"(a3), "r"(b0), "r"(b1));
}

// split a float pair into hi (fp16) and lo (fp16 residual) packed half2 words
__device__ __forceinline__ void split_pack(float x, float y, uint& hi, uint& lo) {
    __half hx = __float2half_rn(x), hy = __float2half_rn(y);
    __half lx = __float2half_rn(x - __half2float(hx));
    __half ly = __float2half_rn(y - __half2float(hy));
    __half2 H = __halves2half2(hx, hy), L = __halves2half2(lx, ly);
    hi = *reinterpret_cast<uint*>(&H);
    lo = *reinterpret_cast<uint*>(&L);
}

// ===========================================================================
// K1: xa[b,t,g] = seq[b,t,:]·WaK[:,g] + ba[g]  via split-fp16 HMMA.
// grid (512, 16): block = (batch row, 64-step chunk). 160 threads = 5 warps;
// warp w owns g in [32w, 32w+32) (2 m16 tiles as A = WaK^T, row-major).
// x tile staged to smem as hi/lo halfs (rows padded to 72 halfs: B-frag LDS
// bank = 4*gID + tq + 8*ks -> conflict-free). D = Wh·xh + Wh·xl + Wl·xh; the
// dropped lo·lo term is ~2^-21 relative. ONE barrier per block.
// ===========================================================================
__global__ void __launch_bounds__(160)
xa_mma(const float* __restrict__ seq, const float* __restrict__ WaK,
       const float* __restrict__ ba)
{
    __shared__ __half sxh[64 * 72];
    __shared__ __half sxl[64 * 72];
    const int b = blockIdx.x, t0 = blockIdx.y * 64;
    const int tid = threadIdx.x, w = tid >> 5, lane = tid & 31;
    const int gID = lane >> 2, tq = lane & 3;
    const int g0 = w * 32;

    // stage + split x tile (64 rows x 64 cols)
    for (int idx = tid; idx < 64 * 64; idx += 160) {
        const int r = idx >> 6, cx = idx & 63;
        const float v = seq[((size_t)b * Tq + t0 + r) * F_IN + cx];
        const __half h = __float2half_rn(v);
        sxh[r * 72 + cx] = h;
        sxl[r * 72 + cx] = __float2half_rn(v - __half2float(h));
    }

    // W fragments (A = WaK^T row-major 16x16 tiles): hi + lo
    uint whi[2][4][4], wlo[2][4][4];
    #pragma unroll
    for (int mt = 0; mt < 2; mt++)
    #pragma unroll
    for (int ks = 0; ks < 4; ks++) {
        const int gc = g0 + mt * 16 + gID;
        const int k0 = ks * 16 + tq * 2;
        split_pack(WaK[k0 * G4 + gc],           WaK[(k0 + 1) * G4 + gc],
                   whi[mt][ks][0], wlo[mt][ks][0]);
        split_pack(WaK[k0 * G4 + gc + 8],       WaK[(k0 + 1) * G4 + gc + 8],
                   whi[mt][ks][1], wlo[mt][ks][1]);
        split_pack(WaK[(k0 + 8) * G4 + gc],     WaK[(k0 + 9) * G4 + gc],
                   whi[mt][ks][2], wlo[mt][ks][2]);
        split_pack(WaK[(k0 + 8) * G4 + gc + 8], WaK[(k0 + 9) * G4 + gc + 8],
                   whi[mt][ks][3], wlo[mt][ks][3]);
    }
    const float bias00 = ba[g0 + gID],      bias01 = ba[g0 + gID + 8];
    const float bias10 = ba[g0 + 16 + gID], bias11 = ba[g0 + 16 + gID + 8];
    __syncthreads();

    #pragma unroll
    for (int nt = 0; nt < 8; nt++) {
        float c[2][4];
        c[0][0] = c[0][1] = bias00; c[0][2] = c[0][3] = bias01;
        c[1][0] = c[1][1] = bias10; c[1][2] = c[1][3] = bias11;
        const int row = nt * 8 + gID;
        #pragma unroll
        for (int ks = 0; ks < 4; ks++) {
            const int cw = ks * 16 + tq * 2;
            const uint bh0 = *(const uint*)&sxh[row * 72 + cw];
            const uint bh1 = *(const uint*)&sxh[row * 72 + cw + 8];
            const uint bl0 = *(const uint*)&sxl[row * 72 + cw];
            const uint bl1 = *(const uint*)&sxl[row * 72 + cw + 8];
            #pragma unroll
            for (int mt = 0; mt < 2; mt++) {
                mma16816(c[mt][0], c[mt][1], c[mt][2], c[mt][3],
                         whi[mt][ks][0], whi[mt][ks][1], whi[mt][ks][2], whi[mt][ks][3],
                         bh0, bh1);
                mma16816(c[mt][0], c[mt][1], c[mt][2], c[mt][3],
                         whi[mt][ks][0], whi[mt][ks][1], whi[mt][ks][2], whi[mt][ks][3],
                         bl0, bl1);
                mma16816(c[mt][0], c[mt][1], c[mt][2], c[mt][3],
                         wlo[mt][ks][0], wlo[mt][ks][1], wlo[mt][ks][2], wlo[mt][ks][3],
                         bh0, bh1);
            }
        }
        const int tc = t0 + nt * 8 + tq * 2;
        #pragma unroll
        for (int mt = 0; mt < 2; mt++) {
            const int gr = g0 + mt * 16 + gID;
            float* o = g_xa + ((size_t)b * Tq + tc) * G4 + gr;
            o[0]      = c[mt][0];
            o[G4]     = c[mt][1];
            o[8]      = c[mt][2];
            o[G4 + 8] = c[mt][3];
        }
    }
}

// ===========================================================================
// K3: xb[b,t,g] = hs[b,t,:]·WbK[:,g] + bb[g]  via split-fp16 HMMA.
// Same design; K padded 40 -> 48 (3 k-steps, zero rows 40..47). hs tile rows
// padded to 56 halfs (bank = tq - 4*gID + 8*ks mod 32, conflict-free).
// ===========================================================================
__global__ void __launch_bounds__(160)
xb_mma(const float* __restrict__ WbK, const float* __restrict__ bb)
{
    __shared__ __half sxh[64 * 56];
    __shared__ __half sxl[64 * 56];
    const int b = blockIdx.x, t0 = blockIdx.y * 64;
    const int tid = threadIdx.x, w = tid >> 5, lane = tid & 31;
    const int gID = lane >> 2, tq = lane & 3;
    const int g0 = w * 32;

    // stage + split hs tile (64 rows x 48 cols; cols 40..47 zero)
    for (int idx = tid; idx < 64 * 48; idx += 160) {
        const int r = idx / 48, cx = idx % 48;
        float v = 0.0f;
        if (cx < HDIM)
            v = g_hs[((size_t)b * Tq + t0 + r) * HDIM + cx];
        const __half h = __float2half_rn(v);
        sxh[r * 56 + cx] = h;
        sxl[r * 56 + cx] = __float2half_rn(v - __half2float(h));
    }

    // W fragments: rows >= 40 are zero
    uint whi[2][3][4], wlo[2][3][4];
    #pragma unroll
    for (int mt = 0; mt < 2; mt++)
    #pragma unroll
    for (int ks = 0; ks < 3; ks++) {
        const int gc = g0 + mt * 16 + gID;
        const int k0 = ks * 16 + tq * 2;
        #pragma unroll
        for (int fi = 0; fi < 4; fi++) {
            const int kk = k0 + ((fi >= 2) ? 8 : 0);
            const int gg = gc + ((fi & 1) ? 8 : 0);
            const float p = (kk     < HDIM) ? WbK[kk * G4 + gg]       : 0.0f;
            const float q = (kk + 1 < HDIM) ? WbK[(kk + 1) * G4 + gg] : 0.0f;
            split_pack(p, q, whi[mt][ks][fi], wlo[mt][ks][fi]);
        }
    }
    const float bias00 = bb[g0 + gID],      bias01 = bb[g0 + gID + 8];
    const float bias10 = bb[g0 + 16 + gID], bias11 = bb[g0 + 16 + gID + 8];
    __syncthreads();

    #pragma unroll
    for (int nt = 0; nt < 8; nt++) {
        float c[2][4];
        c[0][0] = c[0][1] = bias00; c[0][2] = c[0][3] = bias01;
        c[1][0] = c[1][1] = bias10; c[1][2] = c[1][3] = bias11;
        const int row = nt * 8 + gID;
        #pragma unroll
        for (int ks = 0; ks < 3; ks++) {
            const int cw = ks * 16 + tq * 2;
            const uint bh0 = *(const uint*)&sxh[row * 56 + cw];
            const uint bh1 = *(const uint*)&sxh[row * 56 + cw + 8];
            const uint bl0 = *(const uint*)&sxl[row * 56 + cw];
            const uint bl1 = *(const uint*)&sxl[row * 56 + cw + 8];
            #pragma unroll
            for (int mt = 0; mt < 2; mt++) {
                mma16816(c[mt][0], c[mt][1], c[mt][2], c[mt][3],
                         whi[mt][ks][0], whi[mt][ks][1], whi[mt][ks][2], whi[mt][ks][3],
                         bh0, bh1);
                mma16816(c[mt][0], c[mt][1], c[mt][2], c[mt][3],
                         whi[mt][ks][0], whi[mt][ks][1], whi[mt][ks][2], whi[mt][ks][3],
                         bl0, bl1);
                mma16816(c[mt][0], c[mt][1], c[mt][2], c[mt][3],
                         wlo[mt][ks][0], wlo[mt][ks][1], wlo[mt][ks][2], wlo[mt][ks][3],
                         bh0, bh1);
            }
        }
        const int tc = t0 + nt * 8 + tq * 2;
        #pragma unroll
        for (int mt = 0; mt < 2; mt++) {
            const int gr = g0 + mt * 16 + gID;
            float* o = g_xb + ((size_t)b * Tq + tc) * G4 + gr;
            o[0]      = c[mt][0];
            o[G4]     = c[mt][1];
            o[8]      = c[mt][2];
            o[G4 + 8] = c[mt][3];
        }
    }
}

// ===========================================================================
// K2: LSTM A recurrence (verified R10/R13, 445us).
// ===========================================================================
__global__ void __launch_bounds__(160)
recur_a(const float* __restrict__ Wr)
{
    __shared__ __align__(16) float sxa[8][G4];
    __shared__ __align__(16) float sh[2][HDIM];

    const int b = blockIdx.x, tid = threadIdx.x;
    const int lane = tid & 31, q = lane >> 3, u = lane & 7, w = tid >> 5;
    const int j = w * 8 + u;
    const int col = q * HDIM + j;

    const bool isG = (q == 2);
    const float mm  = isG ? -2.8853900817779268f : -1.4426950408889634f;
    const float aa  = isG ? 2.0f : 1.0f;
    const float bbv = isG ? -1.0f : 0.0f;

    ull wr2[20];
    #pragma unroll
    for (int p = 0; p < 20; p++)
        wr2[p] = pack2(Wr[(2 * p) * G4 + col], Wr[(2 * p + 1) * G4 + col]);

    float c = 0.0f;
    if (tid < HDIM) sh[0][tid] = 0.0f;

    const float* srcb = g_xa + (size_t)b * Tq * G4;

    if (tid < 40) {
        #pragma unroll
        for (int p = 0; p < 4; p++) {
            unsigned dst = smem_u32(&sxa[p][tid * 4]);
            asm volatile("cp.async.ca.shared.global [%0], [%1], 16;\n\t"
                         "cp.async.commit_group;\n"
                         :: "r"(dst), "l"(srcb + (size_t)p * G4 + tid * 4));
        }
        asm volatile("cp.async.wait_group 3;");
    }
    __syncthreads();

    for (int t = 0; t < Tq; t++) {
        if (tid < 40) {
            const int tf = t + 4;
            if (tf < Tq) {
                unsigned dst = smem_u32(&sxa[tf & 7][tid * 4]);
                asm volatile("cp.async.ca.shared.global [%0], [%1], 16;"
                             :: "r"(dst), "l"(srcb + (size_t)tf * G4 + tid * 4));
            }
            asm volatile("cp.async.commit_group;\n\t"
                         "cp.async.wait_group 3;\n");
        }

        const float xz = sxa[t & 7][col];
        const ulonglong2* h2 = (const ulonglong2*)sh[t & 1];
        ull a0 = 0ull, a1 = 0ull;
        #pragma unroll
        for (int p = 0; p < 10; p++) {
            ulonglong2 hv = h2[p];
            ffma2(a0, wr2[2 * p],     hv.x);
            ffma2(a1, wr2[2 * p + 1], hv.y);
        }
        float x0, x1, x2, x3;
        unpack2(a0, x0, x1); unpack2(a1, x2, x3);
        const float z = xz + ((x0 + x2) + (x1 + x3));
        const float v = gate_act(z, mm, aa, bbv);

        const float fv = __shfl_xor_sync(0xffffffffu, v, 8);
        const float gv = __shfl_xor_sync(0xffffffffu, v, 16);
        const float ov = __shfl_xor_sync(0xffffffffu, v, 24);
        if (q == 0) {
            c = fmaf(fv, c, v * gv);
            const float h = ov * tanh_f(c);
            sh[(t + 1) & 1][j] = h;
            g_hs[((size_t)b * Tq + t) * HDIM + j] = h;
        }
        __syncthreads();
    }
}

// ===========================================================================
// K4: LSTM B recurrence + fused dense tail (verified R13, 441us).
// ===========================================================================
__global__ void __launch_bounds__(160)
recur_b_tail(const float* __restrict__ Wr,
             const float* __restrict__ feat,
             const float* __restrict__ Wg, const float* __restrict__ bg,
             const float* __restrict__ Wh, const float* __restrict__ bh,
             const float* __restrict__ Wc, const float* __restrict__ bc,
             const float* __restrict__ Wd, const float* __restrict__ bd,
             const float* __restrict__ Wo, const float* __restrict__ bo,
             float* __restrict__ out)
{
    __shared__ __align__(16) float sxa[8][G4];
    __shared__ __align__(16) float sh[2][HDIM];
    __shared__ float t1[10], yy[10], cc[20], dd[10];

    const int b = blockIdx.x, tid = threadIdx.x;
    const int lane = tid & 31, q = lane >> 3, u = lane & 7, w = tid >> 5;
    const int j = w * 8 + u;
    const int col = q * HDIM + j;

    const bool isG = (q == 2);
    const float mm  = isG ? -2.8853900817779268f : -1.4426950408889634f;
    const float aa  = isG ? 2.0f : 1.0f;
    const float bbv = isG ? -1.0f : 0.0f;

    ull wr2[20];
    #pragma unroll
    for (int p = 0; p < 20; p++)
        wr2[p] = pack2(Wr[(2 * p) * G4 + col], Wr[(2 * p + 1) * G4 + col]);

    float c = 0.0f;
    if (tid < HDIM) sh[0][tid] = 0.0f;

    const float* srcb = g_xb + (size_t)b * Tq * G4;

    if (tid < 40) {
        #pragma unroll
        for (int p = 0; p < 4; p++) {
            unsigned dst = smem_u32(&sxa[p][tid * 4]);
            asm volatile("cp.async.ca.shared.global [%0], [%1], 16;\n\t"
                         "cp.async.commit_group;\n"
                         :: "r"(dst), "l"(srcb + (size_t)p * G4 + tid * 4));
        }
        asm volatile("cp.async.wait_group 3;");
    }
    __syncthreads();

    for (int t = 0; t < Tq; t++) {
        if (tid < 40) {
            const int tf = t + 4;
            if (tf < Tq) {
                unsigned dst = smem_u32(&sxa[tf & 7][tid * 4]);
                asm volatile("cp.async.ca.shared.global [%0], [%1], 16;"
                             :: "r"(dst), "l"(srcb + (size_t)tf * G4 + tid * 4));
            }
            asm volatile("cp.async.commit_group;\n\t"
                         "cp.async.wait_group 3;\n");
        }

        const float xz = sxa[t & 7][col];
        const ulonglong2* h2 = (const ulonglong2*)sh[t & 1];
        ull a0 = 0ull, a1 = 0ull;
        #pragma unroll
        for (int p = 0; p < 10; p++) {
            ulonglong2 hv = h2[p];
            ffma2(a0, wr2[2 * p],     hv.x);
            ffma2(a1, wr2[2 * p + 1], hv.y);
        }
        float x0, x1, x2, x3;
        unpack2(a0, x0, x1); unpack2(a1, x2, x3);
        const float z = xz + ((x0 + x2) + (x1 + x3));
        const float v = gate_act(z, mm, aa, bbv);

        const float fv = __shfl_xor_sync(0xffffffffu, v, 8);
        const float gv = __shfl_xor_sync(0xffffffffu, v, 16);
        const float ov = __shfl_xor_sync(0xffffffffu, v, 24);
        if (q == 0) {
            c = fmaf(fv, c, v * gv);
            sh[(t + 1) & 1][j] = ov * tanh_f(c);
        }
        __syncthreads();
    }

    // ---- fused dense tail for row b ----
    const float* hb = sh[Tq & 1];
    const float* fb = feat + (size_t)b * F_IN;
    if (tid < 10) {
        float a = bg[tid];
        #pragma unroll 8
        for (int k = 0; k < F_IN; k++) a = fmaf(fb[k], Wg[k * 10 + tid], a);
        t1[tid] = tanh_f(a);
    }
    __syncthreads();
    if (tid < 10) {
        float a = bh[tid];
        #pragma unroll
        for (int k = 0; k < 10; k++) a = fmaf(t1[k], Wh[k * 10 + tid], a);
        yy[tid] = tanh_f(a);
    }
    __syncthreads();
    if (tid < 20) {
        float a = bc[tid];
        #pragma unroll
        for (int k = 0; k < HDIM; k++) a = fmaf(hb[k], Wc[k * 20 + tid], a);
        #pragma unroll
        for (int k = 0; k < 10; k++)   a = fmaf(yy[k], Wc[(HDIM + k) * 20 + tid], a);
        cc[tid] = fmaxf(a, 0.0f);
    }
    __syncthreads();
    if (tid < 10) {
        float a = bd[tid];
        #pragma unroll
        for (int k = 0; k < 20; k++) a = fmaf(cc[k], Wd[k * 10 + tid], a);
        dd[tid] = fmaxf(a, 0.0f);
    }
    __syncthreads();
    if (tid == 0) {
        float a = bo[0];
        #pragma unroll
        for (int k = 0; k < 10; k++) a = fmaf(dd[k], Wo[k], a);
        out[b] = sigmoid_f(a);
    }
}

// ---------------------------------------------------------------------------
extern "C" void kernel_launch(void* const* d_in, const int* in_sizes, int n_in,
                              void* d_out, int out_size)
{
    (void)in_sizes; (void)n_in; (void)out_size;
    const float* seq  = (const float*)d_in[0];
    const float* feat = (const float*)d_in[1];
    const float* WaK  = (const float*)d_in[2];
    const float* WaR  = (const float*)d_in[3];
    const float* ba   = (const float*)d_in[4];
    const float* WbK  = (const float*)d_in[5];
    const float* WbR  = (const float*)d_in[6];
    const float* bb   = (const float*)d_in[7];
    const float* Wg   = (const float*)d_in[8];
    const float* bg   = (const float*)d_in[9];
    const float* Wh   = (const float*)d_in[10];
    const float* bh   = (const float*)d_in[11];
    const float* Wc   = (const float*)d_in[12];
    const float* bc   = (const float*)d_in[13];
    const float* Wd   = (const float*)d_in[14];
    const float* bd   = (const float*)d_in[15];
    const float* Wo   = (const float*)d_in[16];
    const float* bo   = (const float*)d_in[17];
    float* out = (float*)d_out;

    xa_mma<<<dim3(512, 16), 160>>>(seq, WaK, ba);
    recur_a<<<512, 160>>>(WaR);
    xb_mma<<<dim3(512, 16), 160>>>(WbK, bb);
    recur_b_tail<<<512, 160>>>(WbR, feat, Wg, bg, Wh, bh, Wc, bc,
                               Wd, bd, Wo, bo, out);
}